// round 1
// baseline (speedup 1.0000x reference)
#include <cuda_runtime.h>
#include <cuda_bf16.h>
#include <math.h>

// Problem constants
#define BATCH   2
#define SEQ     2048
#define DMODEL  1024
#define HEADS   16
#define DHEAD   64
#define INNER   (HEADS * DHEAD)          // 1024
#define BS      (BATCH * SEQ)            // 4096
#define QKV_N   (3 * INNER)              // 3072

// -------------------- scratch (static device allocations) --------------------
__device__ float g_qkv[BS * QKV_N];              // [4096, 3072]
__device__ float g_q[BATCH * HEADS * SEQ * DHEAD];
__device__ float g_k[BATCH * HEADS * SEQ * DHEAD];
__device__ float g_v[BATCH * HEADS * SEQ * DHEAD];
__device__ float g_ctx[BS * INNER];              // [4096, 1024]

// -------------------- SGEMM: C[M,N] = A[M,K] @ B[K,N], all row-major --------
// 128x128 tile, BK=8, 256 threads, 8x8 per-thread register tile.
// Requires M%128==0, N%128==0, K%8==0 (true for all calls here).
__global__ __launch_bounds__(256) void sgemm128(const float* __restrict__ A,
                                                const float* __restrict__ B,
                                                float* __restrict__ C,
                                                int M, int N, int K) {
    __shared__ float As[8][128];   // transposed A tile
    __shared__ float Bs[8][128];

    const int tid  = threadIdx.x;
    const int brow = blockIdx.y * 128;
    const int bcol = blockIdx.x * 128;
    const int ty = tid >> 4;       // 0..15
    const int tx = tid & 15;       // 0..15

    const int arow  = tid >> 1;          // 0..127
    const int acol  = (tid & 1) * 4;     // 0 or 4
    const int brl   = tid >> 5;          // 0..7
    const int bcl   = (tid & 31) * 4;    // 0..124

    float acc[8][8];
    #pragma unroll
    for (int i = 0; i < 8; i++)
        #pragma unroll
        for (int j = 0; j < 8; j++) acc[i][j] = 0.f;

    for (int k0 = 0; k0 < K; k0 += 8) {
        float4 a = *(const float4*)(A + (size_t)(brow + arow) * K + k0 + acol);
        As[acol + 0][arow] = a.x;
        As[acol + 1][arow] = a.y;
        As[acol + 2][arow] = a.z;
        As[acol + 3][arow] = a.w;
        float4 b = *(const float4*)(B + (size_t)(k0 + brl) * N + bcol + bcl);
        *(float4*)(&Bs[brl][bcl]) = b;
        __syncthreads();

        #pragma unroll
        for (int kk = 0; kk < 8; kk++) {
            float ar[8], br[8];
            #pragma unroll
            for (int i = 0; i < 8; i++) ar[i] = As[kk][ty * 8 + i];
            #pragma unroll
            for (int j = 0; j < 8; j++) br[j] = Bs[kk][tx * 8 + j];
            #pragma unroll
            for (int i = 0; i < 8; i++)
                #pragma unroll
                for (int j = 0; j < 8; j++)
                    acc[i][j] = fmaf(ar[i], br[j], acc[i][j]);
        }
        __syncthreads();
    }

    #pragma unroll
    for (int i = 0; i < 8; i++) {
        float* crow = C + (size_t)(brow + ty * 8 + i) * N + bcol + tx * 8;
        float4 r0 = {acc[i][0], acc[i][1], acc[i][2], acc[i][3]};
        float4 r1 = {acc[i][4], acc[i][5], acc[i][6], acc[i][7]};
        *(float4*)(crow)     = r0;
        *(float4*)(crow + 4) = r1;
    }
}

// -------------------- RoPE + split [BS,3072] -> q,k(roped),v [B,H,S,Dh] -----
__global__ __launch_bounds__(256) void rope_split(const float* __restrict__ qkv) {
    int gid = blockIdx.x * blockDim.x + threadIdx.x;   // 0 .. BS*INNER-1
    int d  = gid & 63;
    int h  = (gid >> 6) & (HEADS - 1);
    int bs = gid >> 10;
    int s  = bs & (SEQ - 1);
    int b  = bs >> 11;

    const float* row = qkv + (size_t)bs * QKV_N;
    float qv = row[h * 64 + d];
    float kv = row[INNER + h * 64 + d];
    float vv = row[2 * INNER + h * 64 + d];

    int i = d & 31;
    float inv_freq = powf(10000.f, -(float)i / 32.f);  // 10000^(-2i/64)
    float ang = (float)s * inv_freq;
    float c = cosf(ang), sn = sinf(ang);

    float qo, ko;
    if (d < 32) {
        float q2 = row[h * 64 + d + 32];
        float k2 = row[INNER + h * 64 + d + 32];
        qo = qv * c - q2 * sn;
        ko = kv * c - k2 * sn;
    } else {
        float q2 = row[h * 64 + d - 32];
        float k2 = row[INNER + h * 64 + d - 32];
        qo = qv * c + q2 * sn;
        ko = kv * c + k2 * sn;
    }

    size_t o = (((size_t)(b * HEADS + h)) * SEQ + s) * DHEAD + d;
    g_q[o] = qo;
    g_k[o] = ko;
    g_v[o] = vv;
}

// -------------------- flash attention (fp32, online softmax) ----------------
// Block = one (b,h, 64-query tile). 256 threads. BQ=BKV=64, Dh=64.
// smem: Qst[64][64] d-major, Kst[64][64] d-major, Vs[64][64] row-major,
//       Ps[64][65], mrow/lrow/arow[64]  => 66560 bytes dynamic.
__global__ __launch_bounds__(256) void flash64(const float* __restrict__ Q,
                                               const float* __restrict__ K,
                                               const float* __restrict__ V,
                                               float* __restrict__ out) {
    extern __shared__ float sm[];
    float* Qst  = sm;                    // 4096
    float* Kst  = sm + 4096;             // 4096
    float* Vs   = sm + 8192;             // 4096
    float* Ps   = sm + 12288;            // 64*65 = 4160
    float* mrow = sm + 12288 + 4160;     // 64
    float* lrow = mrow + 64;             // 64
    float* arow = lrow + 64;             // 64

    const int tid = threadIdx.x;
    const int qt  = blockIdx.x & 31;     // SEQ/64
    const int bh  = blockIdx.x >> 5;     // 0..31
    const float* qbase = Q + ((size_t)bh * SEQ + qt * 64) * DHEAD;
    const float* kbase = K + (size_t)bh * SEQ * DHEAD;
    const float* vbase = V + (size_t)bh * SEQ * DHEAD;

    // load Q tile transposed (d-major)
    #pragma unroll
    for (int t = 0; t < 4; t++) {
        int lin = tid + t * 256;          // float4 index, 0..1023
        int r   = lin >> 4;
        int d4  = (lin & 15) * 4;
        float4 q4 = *(const float4*)(qbase + r * 64 + d4);
        Qst[(d4 + 0) * 64 + r] = q4.x;
        Qst[(d4 + 1) * 64 + r] = q4.y;
        Qst[(d4 + 2) * 64 + r] = q4.z;
        Qst[(d4 + 3) * 64 + r] = q4.w;
    }
    if (tid < 64) { mrow[tid] = -INFINITY; lrow[tid] = 0.f; }

    const int ty = tid >> 4, tx = tid & 15;
    float O[4][4];
    #pragma unroll
    for (int i = 0; i < 4; i++)
        #pragma unroll
        for (int j = 0; j < 4; j++) O[i][j] = 0.f;

    const float scale = 0.125f;   // 1/sqrt(64)

    for (int kv0 = 0; kv0 < SEQ; kv0 += 64) {
        __syncthreads();   // previous iter done with Kst/Vs; also covers Q load 1st iter
        #pragma unroll
        for (int t = 0; t < 4; t++) {
            int lin = tid + t * 256;
            int r   = lin >> 4;
            int d4  = (lin & 15) * 4;
            float4 k4 = *(const float4*)(kbase + (size_t)(kv0 + r) * 64 + d4);
            Kst[(d4 + 0) * 64 + r] = k4.x;
            Kst[(d4 + 1) * 64 + r] = k4.y;
            Kst[(d4 + 2) * 64 + r] = k4.z;
            Kst[(d4 + 3) * 64 + r] = k4.w;
            float4 v4 = *(const float4*)(vbase + (size_t)(kv0 + r) * 64 + d4);
            *(float4*)(Vs + r * 64 + d4) = v4;
        }
        __syncthreads();

        // S = Q K^T (64x64), thread tile (4 q-rows, 4 k-rows)
        float sacc[4][4];
        #pragma unroll
        for (int i = 0; i < 4; i++)
            #pragma unroll
            for (int j = 0; j < 4; j++) sacc[i][j] = 0.f;
        #pragma unroll 8
        for (int kk = 0; kk < 64; kk++) {
            float a[4], b[4];
            #pragma unroll
            for (int i = 0; i < 4; i++) a[i] = Qst[kk * 64 + ty * 4 + i];
            #pragma unroll
            for (int j = 0; j < 4; j++) b[j] = Kst[kk * 64 + tx * 4 + j];
            #pragma unroll
            for (int i = 0; i < 4; i++)
                #pragma unroll
                for (int j = 0; j < 4; j++)
                    sacc[i][j] = fmaf(a[i], b[j], sacc[i][j]);
        }
        #pragma unroll
        for (int i = 0; i < 4; i++)
            #pragma unroll
            for (int j = 0; j < 4; j++)
                Ps[(ty * 4 + i) * 65 + tx * 4 + j] = sacc[i][j];
        __syncthreads();

        // online softmax per row (64 threads, one row each; Ps padded -> no conflicts)
        if (tid < 64) {
            float* prow = Ps + tid * 65;
            float m_old = mrow[tid];
            float mx = m_old;
            #pragma unroll 8
            for (int j = 0; j < 64; j++) mx = fmaxf(mx, prow[j] * scale);
            float sum = 0.f;
            #pragma unroll 8
            for (int j = 0; j < 64; j++) {
                float p = __expf(prow[j] * scale - mx);
                prow[j] = p;
                sum += p;
            }
            float corr = __expf(m_old - mx);
            lrow[tid] = lrow[tid] * corr + sum;
            mrow[tid] = mx;
            arow[tid] = corr;
        }
        __syncthreads();

        // O = O*alpha + P @ V  (thread tile: 4 q-rows x 4 dh-cols)
        #pragma unroll
        for (int i = 0; i < 4; i++) {
            float a = arow[ty * 4 + i];
            #pragma unroll
            for (int j = 0; j < 4; j++) O[i][j] *= a;
        }
        #pragma unroll 8
        for (int j = 0; j < 64; j++) {
            float p[4], vv[4];
            #pragma unroll
            for (int i = 0; i < 4; i++) p[i] = Ps[(ty * 4 + i) * 65 + j];
            #pragma unroll
            for (int c = 0; c < 4; c++) vv[c] = Vs[j * 64 + tx * 4 + c];
            #pragma unroll
            for (int i = 0; i < 4; i++)
                #pragma unroll
                for (int c = 0; c < 4; c++)
                    O[i][c] = fmaf(p[i], vv[c], O[i][c]);
        }
    }
    __syncthreads();

    // write ctx in [B, S, H*Dh] layout
    const int b = bh >> 4, h = bh & 15;
    #pragma unroll
    for (int i = 0; i < 4; i++) {
        int r = ty * 4 + i;
        float inv_l = 1.f / lrow[r];
        int srow = qt * 64 + r;
        float4 res = {O[i][0] * inv_l, O[i][1] * inv_l, O[i][2] * inv_l, O[i][3] * inv_l};
        *(float4*)(out + ((size_t)(b * SEQ + srow)) * INNER + h * 64 + tx * 4) = res;
    }
}

// -------------------- launch --------------------
extern "C" void kernel_launch(void* const* d_in, const int* in_sizes, int n_in,
                              void* d_out, int out_size) {
    const float* x     = (const float*)d_in[0];   // [2,2048,1024]
    const float* w_qkv = (const float*)d_in[1];   // [1024,3072]
    const float* w_out = (const float*)d_in[2];   // [1024,1024]
    float* out = (float*)d_out;                   // [2,2048,1024]

    float *qkv, *q, *k, *v, *ctx;
    cudaGetSymbolAddress((void**)&qkv, g_qkv);
    cudaGetSymbolAddress((void**)&q,   g_q);
    cudaGetSymbolAddress((void**)&k,   g_k);
    cudaGetSymbolAddress((void**)&v,   g_v);
    cudaGetSymbolAddress((void**)&ctx, g_ctx);

    // 1) qkv = x @ w_qkv   [4096,1024] x [1024,3072]
    sgemm128<<<dim3(QKV_N / 128, BS / 128), 256>>>(x, w_qkv, qkv, BS, QKV_N, DMODEL);

    // 2) RoPE + head split
    rope_split<<<(BS * INNER) / 256, 256>>>(qkv);

    // 3) flash attention
    static const int kFlashSmem = 66560;
    cudaFuncSetAttribute(flash64, cudaFuncAttributeMaxDynamicSharedMemorySize, kFlashSmem);
    flash64<<<BATCH * HEADS * (SEQ / 64), 256, kFlashSmem>>>(q, k, v, ctx);

    // 4) out = ctx @ w_out   [4096,1024] x [1024,1024]
    sgemm128<<<dim3(DMODEL / 128, BS / 128), 256>>>(ctx, w_out, out, BS, DMODEL, DMODEL);
}

// round 4
// speedup vs baseline: 1.3924x; 1.3924x over previous
#include <cuda_runtime.h>
#include <cuda_bf16.h>
#include <math.h>
#include <stdint.h>

// Problem constants
#define BATCH   2
#define SEQ     2048
#define DMODEL  1024
#define HEADS   16
#define DHEAD   64
#define INNER   (HEADS * DHEAD)          // 1024
#define BS      (BATCH * SEQ)            // 4096
#define QKV_N   (3 * INNER)              // 3072
#define KSPLIT  (3 * DMODEL)             // 3072 (hi | lo | hi split along K)

// -------------------- scratch (static device allocations) --------------------
__device__ float g_qkv[BS * QKV_N];                       // [4096, 3072] fp32
__device__ float g_q[BATCH * HEADS * SEQ * DHEAD];
__device__ float g_k[BATCH * HEADS * SEQ * DHEAD];
__device__ float g_v[BATCH * HEADS * SEQ * DHEAD];
__device__ float g_ctx[BS * INNER];                       // [4096, 1024] fp32
__device__ __nv_bfloat16 g_abuf[BS * KSPLIT];             // split A (x, then ctx)
__device__ __nv_bfloat16 g_bt_qkv[QKV_N * KSPLIT];        // split w_qkv^T
__device__ __nv_bfloat16 g_bt_out[DMODEL * KSPLIT];       // split w_out^T

// ==================== PTX helpers (sm_80-era, safe at compute_100) ===========
__device__ __forceinline__ uint32_t smem_u32(const void* p) {
    return (uint32_t)__cvta_generic_to_shared(p);
}
__device__ __forceinline__ void cp_async16(uint32_t dst, const void* src) {
    asm volatile("cp.async.cg.shared.global [%0], [%1], 16;\n" :: "r"(dst), "l"(src));
}
__device__ __forceinline__ void cp_commit() {
    asm volatile("cp.async.commit_group;\n" ::: "memory");
}
__device__ __forceinline__ void ldmatrix_x4(uint32_t* r, uint32_t addr) {
    asm volatile("ldmatrix.sync.aligned.m8n8.x4.shared.b16 {%0,%1,%2,%3}, [%4];"
                 : "=r"(r[0]), "=r"(r[1]), "=r"(r[2]), "=r"(r[3]) : "r"(addr));
}
__device__ __forceinline__ void mma16816(float* c, const uint32_t* a,
                                         uint32_t b0, uint32_t b1) {
    asm volatile(
        "mma.sync.aligned.m16n8k16.row.col.f32.bf16.bf16.f32 "
        "{%0,%1,%2,%3}, {%4,%5,%6,%7}, {%8,%9}, {%0,%1,%2,%3};"
        : "+f"(c[0]), "+f"(c[1]), "+f"(c[2]), "+f"(c[3])
        : "r"(a[0]), "r"(a[1]), "r"(a[2]), "r"(a[3]), "r"(b0), "r"(b1));
}

// ==================== conversion kernels (hi/lo bf16 split) ====================
// in [M,1024] fp32 row-major -> out [M,3072] bf16:  [hi | lo | hi]
__global__ __launch_bounds__(256) void split_rows(const float* __restrict__ in,
                                                  __nv_bfloat16* __restrict__ out) {
    int idx = blockIdx.x * 256 + threadIdx.x;       // quad index
    int m  = idx >> 8;                               // 1024/4 = 256 quads/row
    int kq = idx & 255;
    float4 v = ((const float4*)in)[(size_t)m * 256 + kq];
    __nv_bfloat16 h0 = __float2bfloat16(v.x), h1 = __float2bfloat16(v.y);
    __nv_bfloat16 h2 = __float2bfloat16(v.z), h3 = __float2bfloat16(v.w);
    __nv_bfloat16 l0 = __float2bfloat16(v.x - __bfloat162float(h0));
    __nv_bfloat16 l1 = __float2bfloat16(v.y - __bfloat162float(h1));
    __nv_bfloat16 l2 = __float2bfloat16(v.z - __bfloat162float(h2));
    __nv_bfloat16 l3 = __float2bfloat16(v.w - __bfloat162float(h3));
    __nv_bfloat162 hA = {h0, h1}, hB = {h2, h3};
    __nv_bfloat162 lA = {l0, l1}, lB = {l2, l3};
    __nv_bfloat162* o = (__nv_bfloat162*)(out + (size_t)m * KSPLIT + kq * 4);
    o[0] = hA; o[1] = hB;                            // [0,1024): hi
    o[512] = lA; o[513] = lB;                        // [1024,2048): lo
    o[1024] = hA; o[1025] = hB;                      // [2048,3072): hi
}

// W [K,N] fp32 -> BT [N,3K] bf16 with [hi | hi | lo] along k'
__global__ __launch_bounds__(256) void split_bt(const float* __restrict__ W,
                                                __nv_bfloat16* __restrict__ BT,
                                                int K, int N) {
    __shared__ float tile[32][33];
    int k0 = blockIdx.x * 32, n0 = blockIdx.y * 32;
    for (int i = threadIdx.x; i < 1024; i += 256) {
        int r = i >> 5, c = i & 31;
        tile[r][c] = W[(size_t)(k0 + r) * N + n0 + c];
    }
    __syncthreads();
    for (int i = threadIdx.x; i < 1024; i += 256) {
        int rn = i >> 5, kc = i & 31;
        float v = tile[kc][rn];
        __nv_bfloat16 hi = __float2bfloat16(v);
        __nv_bfloat16 lo = __float2bfloat16(v - __bfloat162float(hi));
        __nv_bfloat16* row = BT + (size_t)(n0 + rn) * (3 * K) + k0 + kc;
        row[0]     = hi;
        row[K]     = hi;
        row[2 * K] = lo;
    }
}

// ==================== HMMA bf16 GEMM (mma.sync) ====================
// C[M,N] fp32 = A[M,Kp] bf16 @ BT[N,Kp]^T bf16.
// CTA tile 128x128, BK=64 (128B rows, SW128 swizzle), double-buffered cp.async.
// 256 threads = 8 warps in 2x4: warp tile 64x32.
__global__ __launch_bounds__(256) void bf16gemm_mma(const __nv_bfloat16* __restrict__ A,
                                                    const __nv_bfloat16* __restrict__ BT,
                                                    float* __restrict__ C,
                                                    int M, int N, int Kp) {
    extern __shared__ __align__(1024) char smem[];
    const uint32_t base = smem_u32(smem);
    const int tid  = threadIdx.x;
    const int wid  = tid >> 5;
    const int lane = tid & 31;
    const int wr   = wid >> 2;       // 0..1  (warp row -> 64 rows)
    const int wc   = wid & 3;        // 0..3  (warp col -> 32 cols)

    const int brow = blockIdx.y * 128;
    const int bcol = blockIdx.x * 128;
    const int nc   = Kp / 64;

    const __nv_bfloat16* Abase = A + (size_t)brow * Kp;
    const __nv_bfloat16* Bbase = BT + (size_t)bcol * Kp;

    // stage s: A at s*32768, B at s*32768 + 16384 (each 128 rows x 128B)
    auto load_stage = [&](int chunk, int s) {
        uint32_t sa = base + s * 32768;
        uint32_t sb = sa + 16384;
        const __nv_bfloat16* ac = Abase + chunk * 64;
        const __nv_bfloat16* bc = Bbase + chunk * 64;
        #pragma unroll
        for (int i = 0; i < 4; i++) {
            int l = tid + i * 256;            // 0..1023: 16B chunk index
            int r = l >> 3;                   // row 0..127
            int c = l & 7;                    // 16B chunk within 128B row
            uint32_t off = (uint32_t)(r * 128 + c * 16);
            uint32_t sw = off ^ ((off >> 3) & 0x70);
            cp_async16(sa + sw, ac + (size_t)r * Kp + c * 8);
            cp_async16(sb + sw, bc + (size_t)r * Kp + c * 8);
        }
        cp_commit();
    };

    float acc[4][4][4];
    #pragma unroll
    for (int mi = 0; mi < 4; mi++)
        #pragma unroll
        for (int ni = 0; ni < 4; ni++)
            #pragma unroll
            for (int j = 0; j < 4; j++) acc[mi][ni][j] = 0.f;

    load_stage(0, 0);
    load_stage(1, 1);

    // ldmatrix address components (constant per thread)
    const int a_row_off = wr * 64 + (lane & 15);      // + mi*16
    const int a_chunk_h = lane >> 4;                  // + ks*2
    const int b_row_off = wc * 32 + ((lane >> 4) << 3) + (lane & 7);  // + g*16
    const int b_chunk_h = (lane >> 3) & 1;            // + ks*2

    for (int c = 0; c < nc; c++) {
        int s = c & 1;
        if (c + 1 < nc) asm volatile("cp.async.wait_group 1;" ::: "memory");
        else            asm volatile("cp.async.wait_group 0;" ::: "memory");
        __syncthreads();

        uint32_t sa = base + s * 32768;
        uint32_t sb = sa + 16384;

        #pragma unroll
        for (int ks = 0; ks < 4; ks++) {
            uint32_t a[4][4];
            #pragma unroll
            for (int mi = 0; mi < 4; mi++) {
                uint32_t off = (uint32_t)((a_row_off + mi * 16) * 128
                                          + (ks * 2 + a_chunk_h) * 16);
                ldmatrix_x4(a[mi], sa + (off ^ ((off >> 3) & 0x70)));
            }
            uint32_t b[2][4];
            #pragma unroll
            for (int g = 0; g < 2; g++) {
                uint32_t off = (uint32_t)((b_row_off + g * 16) * 128
                                          + (ks * 2 + b_chunk_h) * 16);
                ldmatrix_x4(b[g], sb + (off ^ ((off >> 3) & 0x70)));
            }
            #pragma unroll
            for (int mi = 0; mi < 4; mi++)
                #pragma unroll
                for (int ni = 0; ni < 4; ni++)
                    mma16816(acc[mi][ni], a[mi],
                             b[ni >> 1][(ni & 1) * 2], b[ni >> 1][(ni & 1) * 2 + 1]);
        }
        __syncthreads();
        if (c + 2 < nc) load_stage(c + 2, s);
    }

    // epilogue: direct fp32 stores (float2 per fragment row)
    #pragma unroll
    for (int mi = 0; mi < 4; mi++) {
        int row0 = brow + wr * 64 + mi * 16 + (lane >> 2);
        #pragma unroll
        for (int ni = 0; ni < 4; ni++) {
            int col = bcol + wc * 32 + ni * 8 + (lane & 3) * 2;
            float2 v0 = {acc[mi][ni][0], acc[mi][ni][1]};
            float2 v1 = {acc[mi][ni][2], acc[mi][ni][3]};
            *(float2*)(C + (size_t)row0 * N + col) = v0;
            *(float2*)(C + (size_t)(row0 + 8) * N + col) = v1;
        }
    }
}

// -------------------- RoPE + split [BS,3072] -> q,k(roped),v [B,H,S,Dh] -----
__global__ __launch_bounds__(256) void rope_split(const float* __restrict__ qkv) {
    int gid = blockIdx.x * blockDim.x + threadIdx.x;   // 0 .. BS*INNER-1
    int d  = gid & 63;
    int h  = (gid >> 6) & (HEADS - 1);
    int bs = gid >> 10;
    int s  = bs & (SEQ - 1);
    int b  = bs >> 11;

    const float* row = qkv + (size_t)bs * QKV_N;
    float qv = row[h * 64 + d];
    float kv = row[INNER + h * 64 + d];
    float vv = row[2 * INNER + h * 64 + d];

    int i = d & 31;
    float inv_freq = powf(10000.f, -(float)i / 32.f);
    float ang = (float)s * inv_freq;
    float c = cosf(ang), sn = sinf(ang);

    float qo, ko;
    if (d < 32) {
        float q2 = row[h * 64 + d + 32];
        float k2 = row[INNER + h * 64 + d + 32];
        qo = qv * c - q2 * sn;
        ko = kv * c - k2 * sn;
    } else {
        float q2 = row[h * 64 + d - 32];
        float k2 = row[INNER + h * 64 + d - 32];
        qo = qv * c + q2 * sn;
        ko = kv * c + k2 * sn;
    }

    size_t o = (((size_t)(b * HEADS + h)) * SEQ + s) * DHEAD + d;
    g_q[o] = qo;
    g_k[o] = ko;
    g_v[o] = vv;
}

// -------------------- flash attention (fp32, online softmax) ----------------
__global__ __launch_bounds__(256) void flash64(const float* __restrict__ Q,
                                               const float* __restrict__ K,
                                               const float* __restrict__ V,
                                               float* __restrict__ out) {
    extern __shared__ float sm[];
    float* Qst  = sm;                    // 4096
    float* Kst  = sm + 4096;             // 4096
    float* Vs   = sm + 8192;             // 4096
    float* Ps   = sm + 12288;            // 64*65 = 4160
    float* mrow = sm + 12288 + 4160;     // 64
    float* lrow = mrow + 64;             // 64
    float* arow = lrow + 64;             // 64

    const int tid = threadIdx.x;
    const int qt  = blockIdx.x & 31;
    const int bh  = blockIdx.x >> 5;
    const float* qbase = Q + ((size_t)bh * SEQ + qt * 64) * DHEAD;
    const float* kbase = K + (size_t)bh * SEQ * DHEAD;
    const float* vbase = V + (size_t)bh * SEQ * DHEAD;

    #pragma unroll
    for (int t = 0; t < 4; t++) {
        int lin = tid + t * 256;
        int r   = lin >> 4;
        int d4  = (lin & 15) * 4;
        float4 q4 = *(const float4*)(qbase + r * 64 + d4);
        Qst[(d4 + 0) * 64 + r] = q4.x;
        Qst[(d4 + 1) * 64 + r] = q4.y;
        Qst[(d4 + 2) * 64 + r] = q4.z;
        Qst[(d4 + 3) * 64 + r] = q4.w;
    }
    if (tid < 64) { mrow[tid] = -INFINITY; lrow[tid] = 0.f; }

    const int ty = tid >> 4, tx = tid & 15;
    float O[4][4];
    #pragma unroll
    for (int i = 0; i < 4; i++)
        #pragma unroll
        for (int j = 0; j < 4; j++) O[i][j] = 0.f;

    const float scale = 0.125f;

    for (int kv0 = 0; kv0 < SEQ; kv0 += 64) {
        __syncthreads();
        #pragma unroll
        for (int t = 0; t < 4; t++) {
            int lin = tid + t * 256;
            int r   = lin >> 4;
            int d4  = (lin & 15) * 4;
            float4 k4 = *(const float4*)(kbase + (size_t)(kv0 + r) * 64 + d4);
            Kst[(d4 + 0) * 64 + r] = k4.x;
            Kst[(d4 + 1) * 64 + r] = k4.y;
            Kst[(d4 + 2) * 64 + r] = k4.z;
            Kst[(d4 + 3) * 64 + r] = k4.w;
            float4 v4 = *(const float4*)(vbase + (size_t)(kv0 + r) * 64 + d4);
            *(float4*)(Vs + r * 64 + d4) = v4;
        }
        __syncthreads();

        float sacc[4][4];
        #pragma unroll
        for (int i = 0; i < 4; i++)
            #pragma unroll
            for (int j = 0; j < 4; j++) sacc[i][j] = 0.f;
        #pragma unroll 8
        for (int kk = 0; kk < 64; kk++) {
            float a[4], b[4];
            #pragma unroll
            for (int i = 0; i < 4; i++) a[i] = Qst[kk * 64 + ty * 4 + i];
            #pragma unroll
            for (int j = 0; j < 4; j++) b[j] = Kst[kk * 64 + tx * 4 + j];
            #pragma unroll
            for (int i = 0; i < 4; i++)
                #pragma unroll
                for (int j = 0; j < 4; j++)
                    sacc[i][j] = fmaf(a[i], b[j], sacc[i][j]);
        }
        #pragma unroll
        for (int i = 0; i < 4; i++)
            #pragma unroll
            for (int j = 0; j < 4; j++)
                Ps[(ty * 4 + i) * 65 + tx * 4 + j] = sacc[i][j];
        __syncthreads();

        if (tid < 64) {
            float* prow = Ps + tid * 65;
            float m_old = mrow[tid];
            float mx = m_old;
            #pragma unroll 8
            for (int j = 0; j < 64; j++) mx = fmaxf(mx, prow[j] * scale);
            float sum = 0.f;
            #pragma unroll 8
            for (int j = 0; j < 64; j++) {
                float p = __expf(prow[j] * scale - mx);
                prow[j] = p;
                sum += p;
            }
            float corr = __expf(m_old - mx);
            lrow[tid] = lrow[tid] * corr + sum;
            mrow[tid] = mx;
            arow[tid] = corr;
        }
        __syncthreads();

        #pragma unroll
        for (int i = 0; i < 4; i++) {
            float a = arow[ty * 4 + i];
            #pragma unroll
            for (int j = 0; j < 4; j++) O[i][j] *= a;
        }
        #pragma unroll 8
        for (int j = 0; j < 64; j++) {
            float p[4], vv[4];
            #pragma unroll
            for (int i = 0; i < 4; i++) p[i] = Ps[(ty * 4 + i) * 65 + j];
            #pragma unroll
            for (int c = 0; c < 4; c++) vv[c] = Vs[j * 64 + tx * 4 + c];
            #pragma unroll
            for (int i = 0; i < 4; i++)
                #pragma unroll
                for (int c = 0; c < 4; c++)
                    O[i][c] = fmaf(p[i], vv[c], O[i][c]);
        }
    }
    __syncthreads();

    const int b = bh >> 4, h = bh & 15;
    #pragma unroll
    for (int i = 0; i < 4; i++) {
        int r = ty * 4 + i;
        float inv_l = 1.f / lrow[r];
        int srow = qt * 64 + r;
        float4 res = {O[i][0] * inv_l, O[i][1] * inv_l, O[i][2] * inv_l, O[i][3] * inv_l};
        *(float4*)(out + ((size_t)(b * SEQ + srow)) * INNER + h * 64 + tx * 4) = res;
    }
}

// -------------------- launch --------------------
extern "C" void kernel_launch(void* const* d_in, const int* in_sizes, int n_in,
                              void* d_out, int out_size) {
    const float* x     = (const float*)d_in[0];   // [2,2048,1024]
    const float* w_qkv = (const float*)d_in[1];   // [1024,3072]
    const float* w_out = (const float*)d_in[2];   // [1024,1024]
    float* out = (float*)d_out;                   // [2,2048,1024]

    float *qkv, *q, *k, *v, *ctx;
    __nv_bfloat16 *abuf, *btq, *bto;
    cudaGetSymbolAddress((void**)&qkv,  g_qkv);
    cudaGetSymbolAddress((void**)&q,    g_q);
    cudaGetSymbolAddress((void**)&k,    g_k);
    cudaGetSymbolAddress((void**)&v,    g_v);
    cudaGetSymbolAddress((void**)&ctx,  g_ctx);
    cudaGetSymbolAddress((void**)&abuf, g_abuf);
    cudaGetSymbolAddress((void**)&btq,  g_bt_qkv);
    cudaGetSymbolAddress((void**)&bto,  g_bt_out);

    const int kGemmSmem = 2 * 32768;   // 64 KB
    cudaFuncSetAttribute(bf16gemm_mma, cudaFuncAttributeMaxDynamicSharedMemorySize, kGemmSmem);
    const int kFlashSmem = 66560;
    cudaFuncSetAttribute(flash64, cudaFuncAttributeMaxDynamicSharedMemorySize, kFlashSmem);

    // weight conversions (hi/lo split + transpose)
    split_bt<<<dim3(DMODEL / 32, QKV_N / 32), 256>>>(w_qkv, btq, DMODEL, QKV_N);
    split_bt<<<dim3(INNER / 32, DMODEL / 32), 256>>>(w_out, bto, INNER, DMODEL);

    // 1) qkv = x @ w_qkv  via bf16 3-split HMMA GEMM
    split_rows<<<(BS * DMODEL / 4) / 256, 256>>>(x, abuf);
    bf16gemm_mma<<<dim3(QKV_N / 128, BS / 128), 256, kGemmSmem>>>(abuf, btq, qkv, BS, QKV_N, KSPLIT);

    // 2) RoPE + head split
    rope_split<<<(BS * INNER) / 256, 256>>>(qkv);

    // 3) flash attention (fp32)
    flash64<<<BATCH * HEADS * (SEQ / 64), 256, kFlashSmem>>>(q, k, v, ctx);

    // 4) out = ctx @ w_out  via bf16 3-split HMMA GEMM
    split_rows<<<(BS * INNER / 4) / 256, 256>>>(ctx, abuf);
    bf16gemm_mma<<<dim3(DMODEL / 128, BS / 128), 256, kGemmSmem>>>(abuf, bto, out, BS, DMODEL, KSPLIT);
}

// round 5
// speedup vs baseline: 3.1739x; 2.2794x over previous
#include <cuda_runtime.h>
#include <cuda_bf16.h>
#include <math.h>
#include <stdint.h>

// Problem constants
#define BATCH   2
#define SEQ     2048
#define DMODEL  1024
#define HEADS   16
#define DHEAD   64
#define INNER   (HEADS * DHEAD)          // 1024
#define BS      (BATCH * SEQ)            // 4096
#define QKV_N   (3 * INNER)              // 3072
#define KSPLIT  (3 * DMODEL)             // 3072 (hi | lo | hi split along K)
#define BH      (BATCH * HEADS)          // 32

// -------------------- scratch (static device allocations) --------------------
__device__ float g_qkv[BS * QKV_N];                       // [4096, 3072] fp32
__device__ float g_ctx[BS * INNER];                       // [4096, 1024] fp32
__device__ __nv_bfloat16 g_abuf[BS * KSPLIT];             // split A (x, then ctx)
__device__ __nv_bfloat16 g_bt_qkv[QKV_N * KSPLIT];        // split w_qkv^T
__device__ __nv_bfloat16 g_bt_out[DMODEL * KSPLIT];       // split w_out^T
// attention operands, bf16 hi/lo
__device__ __nv_bfloat16 g_qh[BH * SEQ * DHEAD];          // scaled q hi  [bh,s,d]
__device__ __nv_bfloat16 g_ql[BH * SEQ * DHEAD];          // scaled q lo
__device__ __nv_bfloat16 g_kh[BH * SEQ * DHEAD];
__device__ __nv_bfloat16 g_kl[BH * SEQ * DHEAD];
__device__ __nv_bfloat16 g_vth[BH * DHEAD * SEQ];         // V^T hi [bh,d,s]
__device__ __nv_bfloat16 g_vtl[BH * DHEAD * SEQ];         // V^T lo

// ==================== PTX helpers (sm_80-era, safe at compute_100) ===========
__device__ __forceinline__ uint32_t smem_u32(const void* p) {
    return (uint32_t)__cvta_generic_to_shared(p);
}
__device__ __forceinline__ void cp_async16(uint32_t dst, const void* src) {
    asm volatile("cp.async.cg.shared.global [%0], [%1], 16;\n" :: "r"(dst), "l"(src));
}
__device__ __forceinline__ void cp_commit() {
    asm volatile("cp.async.commit_group;\n" ::: "memory");
}
__device__ __forceinline__ void ldmatrix_x4(uint32_t* r, uint32_t addr) {
    asm volatile("ldmatrix.sync.aligned.m8n8.x4.shared.b16 {%0,%1,%2,%3}, [%4];"
                 : "=r"(r[0]), "=r"(r[1]), "=r"(r[2]), "=r"(r[3]) : "r"(addr));
}
__device__ __forceinline__ void mma16816(float* c, const uint32_t* a,
                                         uint32_t b0, uint32_t b1) {
    asm volatile(
        "mma.sync.aligned.m16n8k16.row.col.f32.bf16.bf16.f32 "
        "{%0,%1,%2,%3}, {%4,%5,%6,%7}, {%8,%9}, {%0,%1,%2,%3};"
        : "+f"(c[0]), "+f"(c[1]), "+f"(c[2]), "+f"(c[3])
        : "r"(a[0]), "r"(a[1]), "r"(a[2]), "r"(a[3]), "r"(b0), "r"(b1));
}
__device__ __forceinline__ uint32_t pack_bf16(float lo, float hi) {
    __nv_bfloat162 v = {__float2bfloat16(lo), __float2bfloat16(hi)};
    return *(uint32_t*)&v;
}
__device__ __forceinline__ uint32_t sw128(uint32_t off) {
    return off ^ ((off >> 3) & 0x70);
}

// ==================== conversion kernels (hi/lo bf16 split) ====================
// in [M,1024] fp32 row-major -> out [M,3072] bf16:  [hi | lo | hi]
__global__ __launch_bounds__(256) void split_rows(const float* __restrict__ in,
                                                  __nv_bfloat16* __restrict__ out) {
    int idx = blockIdx.x * 256 + threadIdx.x;       // quad index
    int m  = idx >> 8;                               // 1024/4 = 256 quads/row
    int kq = idx & 255;
    float4 v = ((const float4*)in)[(size_t)m * 256 + kq];
    __nv_bfloat16 h0 = __float2bfloat16(v.x), h1 = __float2bfloat16(v.y);
    __nv_bfloat16 h2 = __float2bfloat16(v.z), h3 = __float2bfloat16(v.w);
    __nv_bfloat16 l0 = __float2bfloat16(v.x - __bfloat162float(h0));
    __nv_bfloat16 l1 = __float2bfloat16(v.y - __bfloat162float(h1));
    __nv_bfloat16 l2 = __float2bfloat16(v.z - __bfloat162float(h2));
    __nv_bfloat16 l3 = __float2bfloat16(v.w - __bfloat162float(h3));
    __nv_bfloat162 hA = {h0, h1}, hB = {h2, h3};
    __nv_bfloat162 lA = {l0, l1}, lB = {l2, l3};
    __nv_bfloat162* o = (__nv_bfloat162*)(out + (size_t)m * KSPLIT + kq * 4);
    o[0] = hA; o[1] = hB;                            // [0,1024): hi
    o[512] = lA; o[513] = lB;                        // [1024,2048): lo
    o[1024] = hA; o[1025] = hB;                      // [2048,3072): hi
}

// W [K,N] fp32 -> BT [N,3K] bf16 with [hi | hi | lo] along k'
__global__ __launch_bounds__(256) void split_bt(const float* __restrict__ W,
                                                __nv_bfloat16* __restrict__ BT,
                                                int K, int N) {
    __shared__ float tile[32][33];
    int k0 = blockIdx.x * 32, n0 = blockIdx.y * 32;
    for (int i = threadIdx.x; i < 1024; i += 256) {
        int r = i >> 5, c = i & 31;
        tile[r][c] = W[(size_t)(k0 + r) * N + n0 + c];
    }
    __syncthreads();
    for (int i = threadIdx.x; i < 1024; i += 256) {
        int rn = i >> 5, kc = i & 31;
        float v = tile[kc][rn];
        __nv_bfloat16 hi = __float2bfloat16(v);
        __nv_bfloat16 lo = __float2bfloat16(v - __bfloat162float(hi));
        __nv_bfloat16* row = BT + (size_t)(n0 + rn) * (3 * K) + k0 + kc;
        row[0]     = hi;
        row[K]     = hi;
        row[2 * K] = lo;
    }
}

// ==================== HMMA bf16 GEMM (mma.sync) ====================
__global__ __launch_bounds__(256) void bf16gemm_mma(const __nv_bfloat16* __restrict__ A,
                                                    const __nv_bfloat16* __restrict__ BT,
                                                    float* __restrict__ C,
                                                    int M, int N, int Kp) {
    extern __shared__ __align__(1024) char smem[];
    const uint32_t base = smem_u32(smem);
    const int tid  = threadIdx.x;
    const int wid  = tid >> 5;
    const int lane = tid & 31;
    const int wr   = wid >> 2;
    const int wc   = wid & 3;

    const int brow = blockIdx.y * 128;
    const int bcol = blockIdx.x * 128;
    const int nc   = Kp / 64;

    const __nv_bfloat16* Abase = A + (size_t)brow * Kp;
    const __nv_bfloat16* Bbase = BT + (size_t)bcol * Kp;

    auto load_stage = [&](int chunk, int s) {
        uint32_t sa = base + s * 32768;
        uint32_t sb = sa + 16384;
        const __nv_bfloat16* ac = Abase + chunk * 64;
        const __nv_bfloat16* bc = Bbase + chunk * 64;
        #pragma unroll
        for (int i = 0; i < 4; i++) {
            int l = tid + i * 256;
            int r = l >> 3;
            int c = l & 7;
            uint32_t sw = sw128((uint32_t)(r * 128 + c * 16));
            cp_async16(sa + sw, ac + (size_t)r * Kp + c * 8);
            cp_async16(sb + sw, bc + (size_t)r * Kp + c * 8);
        }
        cp_commit();
    };

    float acc[4][4][4];
    #pragma unroll
    for (int mi = 0; mi < 4; mi++)
        #pragma unroll
        for (int ni = 0; ni < 4; ni++)
            #pragma unroll
            for (int j = 0; j < 4; j++) acc[mi][ni][j] = 0.f;

    load_stage(0, 0);
    load_stage(1, 1);

    const int a_row_off = wr * 64 + (lane & 15);
    const int a_chunk_h = lane >> 4;
    const int b_row_off = wc * 32 + ((lane >> 4) << 3) + (lane & 7);
    const int b_chunk_h = (lane >> 3) & 1;

    for (int c = 0; c < nc; c++) {
        int s = c & 1;
        if (c + 1 < nc) asm volatile("cp.async.wait_group 1;" ::: "memory");
        else            asm volatile("cp.async.wait_group 0;" ::: "memory");
        __syncthreads();

        uint32_t sa = base + s * 32768;
        uint32_t sb = sa + 16384;

        #pragma unroll
        for (int ks = 0; ks < 4; ks++) {
            uint32_t a[4][4];
            #pragma unroll
            for (int mi = 0; mi < 4; mi++) {
                uint32_t off = (uint32_t)((a_row_off + mi * 16) * 128
                                          + (ks * 2 + a_chunk_h) * 16);
                ldmatrix_x4(a[mi], sa + sw128(off));
            }
            uint32_t b[2][4];
            #pragma unroll
            for (int g = 0; g < 2; g++) {
                uint32_t off = (uint32_t)((b_row_off + g * 16) * 128
                                          + (ks * 2 + b_chunk_h) * 16);
                ldmatrix_x4(b[g], sb + sw128(off));
            }
            #pragma unroll
            for (int mi = 0; mi < 4; mi++)
                #pragma unroll
                for (int ni = 0; ni < 4; ni++)
                    mma16816(acc[mi][ni], a[mi],
                             b[ni >> 1][(ni & 1) * 2], b[ni >> 1][(ni & 1) * 2 + 1]);
        }
        __syncthreads();
        if (c + 2 < nc) load_stage(c + 2, s);
    }

    #pragma unroll
    for (int mi = 0; mi < 4; mi++) {
        int row0 = brow + wr * 64 + mi * 16 + (lane >> 2);
        #pragma unroll
        for (int ni = 0; ni < 4; ni++) {
            int col = bcol + wc * 32 + ni * 8 + (lane & 3) * 2;
            float2 v0 = {acc[mi][ni][0], acc[mi][ni][1]};
            float2 v1 = {acc[mi][ni][2], acc[mi][ni][3]};
            *(float2*)(C + (size_t)row0 * N + col) = v0;
            *(float2*)(C + (size_t)(row0 + 8) * N + col) = v1;
        }
    }
}

// -------------------- RoPE: qkv -> split bf16 q (scaled), k  [bh,s,d] -------
__global__ __launch_bounds__(256) void rope_qk(const float* __restrict__ qkv) {
    int gid = blockIdx.x * blockDim.x + threadIdx.x;   // 0 .. BS*INNER-1
    int d  = gid & 63;
    int h  = (gid >> 6) & (HEADS - 1);
    int bs = gid >> 10;
    int s  = bs & (SEQ - 1);
    int b  = bs >> 11;

    const float* row = qkv + (size_t)bs * QKV_N;
    float qv = row[h * 64 + d];
    float kv = row[INNER + h * 64 + d];

    int i = d & 31;
    float inv_freq = powf(10000.f, -(float)i / 32.f);
    float ang = (float)s * inv_freq;
    float c = cosf(ang), sn = sinf(ang);

    float qo, ko;
    if (d < 32) {
        float q2 = row[h * 64 + d + 32];
        float k2 = row[INNER + h * 64 + d + 32];
        qo = qv * c - q2 * sn;
        ko = kv * c - k2 * sn;
    } else {
        float q2 = row[h * 64 + d - 32];
        float k2 = row[INNER + h * 64 + d - 32];
        qo = qv * c + q2 * sn;
        ko = kv * c + k2 * sn;
    }
    qo *= 0.125f;   // fold softmax scale into q

    size_t o = (((size_t)(b * HEADS + h)) * SEQ + s) * DHEAD + d;
    __nv_bfloat16 qh = __float2bfloat16(qo);
    __nv_bfloat16 kh = __float2bfloat16(ko);
    g_qh[o] = qh;
    g_ql[o] = __float2bfloat16(qo - __bfloat162float(qh));
    g_kh[o] = kh;
    g_kl[o] = __float2bfloat16(ko - __bfloat162float(kh));
}

// -------------------- V: qkv -> transposed split bf16 V^T [bh,d,s] ----------
__global__ __launch_bounds__(256) void vsplit_t(const float* __restrict__ qkv) {
    __shared__ float tile[64][65];
    int bh = blockIdx.y;                 // 0..31
    int s0 = blockIdx.x * 64;            // seq tile
    int b = bh >> 4, h = bh & 15;
    int tid = threadIdx.x;

    // read 64 s x 64 d (fp32, coalesced)
    for (int t = 0; t < 4; t++) {
        int l = tid + t * 256;           // float4 index: 16 per row
        int r = l >> 4;                  // s row
        int c4 = (l & 15) * 4;           // d col
        float4 v = *(const float4*)(qkv + (size_t)(b * SEQ + s0 + r) * QKV_N
                                    + 2 * INNER + h * 64 + c4);
        tile[r][c4] = v.x; tile[r][c4 + 1] = v.y;
        tile[r][c4 + 2] = v.z; tile[r][c4 + 3] = v.w;
    }
    __syncthreads();

    // write 64 d x 64 s (bf16 hi/lo, coalesced along s)
    for (int t = 0; t < 16; t++) {
        int l = tid + t * 256;
        int d = l >> 6, s = l & 63;
        float v = tile[s][d];
        __nv_bfloat16 hi = __float2bfloat16(v);
        size_t o = ((size_t)bh * DHEAD + d) * SEQ + s0 + s;
        g_vth[o] = hi;
        g_vtl[o] = __float2bfloat16(v - __bfloat162float(hi));
    }
}

// ==================== flash attention via HMMA (hi/lo split) =================
// Block: one (bh, 128-q tile). 8 warps x 16 q rows. KV tiles of 64, double buffered.
// SMEM: Qh(16K) Ql(16K) | stage0: kh kl vth vtl (4x8K) | stage1 (4x8K) = 96KB.
__global__ __launch_bounds__(256) void flash_mma(float* __restrict__ out) {
    extern __shared__ __align__(1024) char smem[];
    const uint32_t base = smem_u32(smem);
    const int tid  = threadIdx.x;
    const int wid  = tid >> 5;
    const int lane = tid & 31;
    const int bh = blockIdx.y;
    const int qt = blockIdx.x;
    const int b = bh >> 4, h = bh & 15;

    const __nv_bfloat16* qhp = g_qh + ((size_t)bh * SEQ + qt * 128) * DHEAD;
    const __nv_bfloat16* qlp = g_ql + ((size_t)bh * SEQ + qt * 128) * DHEAD;

    // load Q tiles (2 x 128 rows x 128B)
    #pragma unroll
    for (int t = 0; t < 4; t++) {
        int l = tid + t * 256;
        int r = l >> 3, c = l & 7;
        uint32_t sw = sw128((uint32_t)(r * 128 + c * 16));
        cp_async16(base + sw,         qhp + (size_t)r * DHEAD + c * 8);
        cp_async16(base + 16384 + sw, qlp + (size_t)r * DHEAD + c * 8);
    }
    cp_commit();

    auto load_kv = [&](int it, int s) {
        uint32_t st = base + 32768 + s * 32768;
        const __nv_bfloat16* khp = g_kh + ((size_t)bh * SEQ + it * 64) * DHEAD;
        const __nv_bfloat16* klp = g_kl + ((size_t)bh * SEQ + it * 64) * DHEAD;
        const __nv_bfloat16* vhp = g_vth + (size_t)bh * DHEAD * SEQ + it * 64;
        const __nv_bfloat16* vlp = g_vtl + (size_t)bh * DHEAD * SEQ + it * 64;
        #pragma unroll
        for (int t = 0; t < 2; t++) {
            int l = tid + t * 256;       // 512 chunks per tile
            int r = l >> 3, c = l & 7;
            uint32_t sw = sw128((uint32_t)(r * 128 + c * 16));
            cp_async16(st + sw,          khp + (size_t)r * DHEAD + c * 8);
            cp_async16(st + 8192 + sw,   klp + (size_t)r * DHEAD + c * 8);
            cp_async16(st + 16384 + sw,  vhp + (size_t)r * SEQ + c * 8);
            cp_async16(st + 24576 + sw,  vlp + (size_t)r * SEQ + c * 8);
        }
        cp_commit();
    };

    load_kv(0, 0);
    load_kv(1, 1);

    const int a_row  = wid * 16 + (lane & 15);
    const int a_chh  = lane >> 4;
    const int b_row  = ((lane >> 4) << 3) + (lane & 7);
    const int b_chh  = (lane >> 3) & 1;

    float Oacc[8][4];
    #pragma unroll
    for (int n = 0; n < 8; n++)
        #pragma unroll
        for (int j = 0; j < 4; j++) Oacc[n][j] = 0.f;
    float m0 = -INFINITY, m1 = -INFINITY, l0 = 0.f, l1 = 0.f;

    const int nIter = SEQ / 64;
    for (int it = 0; it < nIter; it++) {
        int s = it & 1;
        if (it + 1 < nIter) asm volatile("cp.async.wait_group 1;" ::: "memory");
        else                asm volatile("cp.async.wait_group 0;" ::: "memory");
        __syncthreads();

        uint32_t st  = base + 32768 + s * 32768;
        uint32_t sqh = base, sql = base + 16384;
        uint32_t skh = st, skl = st + 8192, svh = st + 16384, svl = st + 24576;

        // ---- S = Qh Kh^T + Ql Kh^T + Qh Kl^T  (fp32-accurate scores) ----
        float sacc[8][4];
        #pragma unroll
        for (int n = 0; n < 8; n++)
            #pragma unroll
            for (int j = 0; j < 4; j++) sacc[n][j] = 0.f;

        #pragma unroll
        for (int pass = 0; pass < 3; pass++) {
            uint32_t at = (pass == 1) ? sql : sqh;
            uint32_t bt = (pass == 2) ? skl : skh;
            #pragma unroll
            for (int ks = 0; ks < 4; ks++) {
                uint32_t a[4];
                ldmatrix_x4(a, at + sw128((uint32_t)(a_row * 128 + (ks * 2 + a_chh) * 16)));
                #pragma unroll
                for (int g = 0; g < 4; g++) {
                    uint32_t bb[4];
                    ldmatrix_x4(bb, bt + sw128((uint32_t)((g * 16 + b_row) * 128
                                               + (ks * 2 + b_chh) * 16)));
                    mma16816(sacc[2 * g],     a, bb[0], bb[1]);
                    mma16816(sacc[2 * g + 1], a, bb[2], bb[3]);
                }
            }
        }

        // ---- register online softmax (rows r=lane/4 and r+8) ----
        float mx0 = m0, mx1 = m1;
        #pragma unroll
        for (int n = 0; n < 8; n++) {
            mx0 = fmaxf(mx0, fmaxf(sacc[n][0], sacc[n][1]));
            mx1 = fmaxf(mx1, fmaxf(sacc[n][2], sacc[n][3]));
        }
        mx0 = fmaxf(mx0, __shfl_xor_sync(0xffffffff, mx0, 1));
        mx0 = fmaxf(mx0, __shfl_xor_sync(0xffffffff, mx0, 2));
        mx1 = fmaxf(mx1, __shfl_xor_sync(0xffffffff, mx1, 1));
        mx1 = fmaxf(mx1, __shfl_xor_sync(0xffffffff, mx1, 2));
        float corr0 = __expf(m0 - mx0);
        float corr1 = __expf(m1 - mx1);
        m0 = mx0; m1 = mx1;

        uint32_t pah[4][4], pal[4][4];
        float sum0 = 0.f, sum1 = 0.f;
        #pragma unroll
        for (int n = 0; n < 8; n++) {
            float p0 = __expf(sacc[n][0] - mx0);
            float p1 = __expf(sacc[n][1] - mx0);
            float p2 = __expf(sacc[n][2] - mx1);
            float p3 = __expf(sacc[n][3] - mx1);
            sum0 += p0 + p1; sum1 += p2 + p3;
            __nv_bfloat16 h0 = __float2bfloat16(p0), h1 = __float2bfloat16(p1);
            __nv_bfloat16 h2 = __float2bfloat16(p2), h3 = __float2bfloat16(p3);
            int ks = n >> 1, hf = (n & 1) * 2;   // frag regs: a0,a1 (n even) / a2,a3 (n odd)
            __nv_bfloat162 ph01 = {h0, h1}, ph23 = {h2, h3};
            pah[ks][hf]     = *(uint32_t*)&ph01;
            pah[ks][hf + 1] = *(uint32_t*)&ph23;
            __nv_bfloat162 pl01 = {__float2bfloat16(p0 - __bfloat162float(h0)),
                                   __float2bfloat16(p1 - __bfloat162float(h1))};
            __nv_bfloat162 pl23 = {__float2bfloat16(p2 - __bfloat162float(h2)),
                                   __float2bfloat16(p3 - __bfloat162float(h3))};
            pal[ks][hf]     = *(uint32_t*)&pl01;
            pal[ks][hf + 1] = *(uint32_t*)&pl23;
        }
        l0 = l0 * corr0 + sum0;
        l1 = l1 * corr1 + sum1;
        #pragma unroll
        for (int n = 0; n < 8; n++) {
            Oacc[n][0] *= corr0; Oacc[n][1] *= corr0;
            Oacc[n][2] *= corr1; Oacc[n][3] *= corr1;
        }

        // ---- O += Ph Vh + Pl Vh + Ph Vl ----
        #pragma unroll
        for (int ks = 0; ks < 4; ks++) {
            #pragma unroll
            for (int g = 0; g < 4; g++) {
                uint32_t off = (uint32_t)((g * 16 + b_row) * 128 + (ks * 2 + b_chh) * 16);
                uint32_t bh_[4], bl_[4];
                ldmatrix_x4(bh_, svh + sw128(off));
                ldmatrix_x4(bl_, svl + sw128(off));
                mma16816(Oacc[2 * g],     pah[ks], bh_[0], bh_[1]);
                mma16816(Oacc[2 * g + 1], pah[ks], bh_[2], bh_[3]);
                mma16816(Oacc[2 * g],     pal[ks], bh_[0], bh_[1]);
                mma16816(Oacc[2 * g + 1], pal[ks], bh_[2], bh_[3]);
                mma16816(Oacc[2 * g],     pah[ks], bl_[0], bl_[1]);
                mma16816(Oacc[2 * g + 1], pah[ks], bl_[2], bl_[3]);
            }
        }

        __syncthreads();
        if (it + 2 < nIter) load_kv(it + 2, s);
    }

    // final normalize + write ctx [B,S,H*Dh]
    l0 += __shfl_xor_sync(0xffffffff, l0, 1);
    l0 += __shfl_xor_sync(0xffffffff, l0, 2);
    l1 += __shfl_xor_sync(0xffffffff, l1, 1);
    l1 += __shfl_xor_sync(0xffffffff, l1, 2);
    float inv0 = 1.f / l0, inv1 = 1.f / l1;
    int row0 = qt * 128 + wid * 16 + (lane >> 2);
    #pragma unroll
    for (int n = 0; n < 8; n++) {
        int col = h * 64 + n * 8 + (lane & 3) * 2;
        float2 v0 = {Oacc[n][0] * inv0, Oacc[n][1] * inv0};
        float2 v1 = {Oacc[n][2] * inv1, Oacc[n][3] * inv1};
        *(float2*)(out + ((size_t)(b * SEQ + row0)) * INNER + col) = v0;
        *(float2*)(out + ((size_t)(b * SEQ + row0 + 8)) * INNER + col) = v1;
    }
}

// -------------------- launch --------------------
extern "C" void kernel_launch(void* const* d_in, const int* in_sizes, int n_in,
                              void* d_out, int out_size) {
    const float* x     = (const float*)d_in[0];   // [2,2048,1024]
    const float* w_qkv = (const float*)d_in[1];   // [1024,3072]
    const float* w_out = (const float*)d_in[2];   // [1024,1024]
    float* out = (float*)d_out;                   // [2,2048,1024]

    float *qkv, *ctx;
    __nv_bfloat16 *abuf, *btq, *bto;
    cudaGetSymbolAddress((void**)&qkv,  g_qkv);
    cudaGetSymbolAddress((void**)&ctx,  g_ctx);
    cudaGetSymbolAddress((void**)&abuf, g_abuf);
    cudaGetSymbolAddress((void**)&btq,  g_bt_qkv);
    cudaGetSymbolAddress((void**)&bto,  g_bt_out);

    const int kGemmSmem = 2 * 32768;   // 64 KB
    cudaFuncSetAttribute(bf16gemm_mma, cudaFuncAttributeMaxDynamicSharedMemorySize, kGemmSmem);
    const int kFlashSmem = 32768 + 2 * 32768;   // 96 KB
    cudaFuncSetAttribute(flash_mma, cudaFuncAttributeMaxDynamicSharedMemorySize, kFlashSmem);

    // weight conversions (hi/lo split + transpose)
    split_bt<<<dim3(DMODEL / 32, QKV_N / 32), 256>>>(w_qkv, btq, DMODEL, QKV_N);
    split_bt<<<dim3(INNER / 32, DMODEL / 32), 256>>>(w_out, bto, INNER, DMODEL);

    // 1) qkv = x @ w_qkv  via bf16 3-split HMMA GEMM
    split_rows<<<(BS * DMODEL / 4) / 256, 256>>>(x, abuf);
    bf16gemm_mma<<<dim3(QKV_N / 128, BS / 128), 256, kGemmSmem>>>(abuf, btq, qkv, BS, QKV_N, KSPLIT);

    // 2) RoPE + hi/lo split of q,k; transposed split of v
    rope_qk<<<(BS * INNER) / 256, 256>>>(qkv);
    vsplit_t<<<dim3(SEQ / 64, BH), 256>>>(qkv);

    // 3) flash attention via HMMA
    flash_mma<<<dim3(SEQ / 128, BH), 256, kFlashSmem>>>(ctx);

    // 4) out = ctx @ w_out  via bf16 3-split HMMA GEMM
    split_rows<<<(BS * INNER / 4) / 256, 256>>>(ctx, abuf);
    bf16gemm_mma<<<dim3(DMODEL / 128, BS / 128), 256, kGemmSmem>>>(abuf, bto, out, BS, DMODEL, KSPLIT);
}

// round 7
// speedup vs baseline: 3.3473x; 1.0546x over previous
#include <cuda_runtime.h>
#include <cuda_bf16.h>
#include <math.h>
#include <stdint.h>

// Problem constants
#define BATCH   2
#define SEQ     2048
#define DMODEL  1024
#define HEADS   16
#define DHEAD   64
#define INNER   (HEADS * DHEAD)          // 1024
#define BS      (BATCH * SEQ)            // 4096
#define QKV_N   (3 * INNER)              // 3072
#define KSPLIT  (3 * DMODEL)             // 3072 (hi | lo | hi split along K)
#define BH      (BATCH * HEADS)          // 32

// -------------------- scratch (static device allocations) --------------------
__device__ float g_qkv[BS * QKV_N];                       // [4096, 3072] fp32
__device__ float g_ctx[BS * INNER];                       // [4096, 1024] fp32
__device__ __nv_bfloat16 g_abuf[BS * KSPLIT];             // split A (x, then ctx)
__device__ __nv_bfloat16 g_bt_qkv[QKV_N * KSPLIT];        // split w_qkv^T
__device__ __nv_bfloat16 g_bt_out[DMODEL * KSPLIT];       // split w_out^T
// attention operands, bf16 hi/lo
__device__ __nv_bfloat16 g_qh[BH * SEQ * DHEAD];          // scaled q hi  [bh,s,d]
__device__ __nv_bfloat16 g_ql[BH * SEQ * DHEAD];          // scaled q lo
__device__ __nv_bfloat16 g_kh[BH * SEQ * DHEAD];
__device__ __nv_bfloat16 g_kl[BH * SEQ * DHEAD];
__device__ __nv_bfloat16 g_vth[BH * DHEAD * SEQ];         // V^T hi [bh,d,s]
__device__ __nv_bfloat16 g_vtl[BH * DHEAD * SEQ];         // V^T lo

// ==================== PTX helpers (sm_80-era, safe at compute_100) ===========
__device__ __forceinline__ uint32_t smem_u32(const void* p) {
    return (uint32_t)__cvta_generic_to_shared(p);
}
__device__ __forceinline__ void cp_async16(uint32_t dst, const void* src) {
    asm volatile("cp.async.cg.shared.global [%0], [%1], 16;\n" :: "r"(dst), "l"(src));
}
__device__ __forceinline__ void cp_commit() {
    asm volatile("cp.async.commit_group;\n" ::: "memory");
}
__device__ __forceinline__ void ldmatrix_x4(uint32_t* r, uint32_t addr) {
    asm volatile("ldmatrix.sync.aligned.m8n8.x4.shared.b16 {%0,%1,%2,%3}, [%4];"
                 : "=r"(r[0]), "=r"(r[1]), "=r"(r[2]), "=r"(r[3]) : "r"(addr));
}
__device__ __forceinline__ void mma16816(float* c, const uint32_t* a,
                                         uint32_t b0, uint32_t b1) {
    asm volatile(
        "mma.sync.aligned.m16n8k16.row.col.f32.bf16.bf16.f32 "
        "{%0,%1,%2,%3}, {%4,%5,%6,%7}, {%8,%9}, {%0,%1,%2,%3};"
        : "+f"(c[0]), "+f"(c[1]), "+f"(c[2]), "+f"(c[3])
        : "r"(a[0]), "r"(a[1]), "r"(a[2]), "r"(a[3]), "r"(b0), "r"(b1));
}
__device__ __forceinline__ uint32_t sw128(uint32_t off) {
    return off ^ ((off >> 3) & 0x70);
}

// ==================== conversion kernels (hi/lo bf16 split) ====================
// in [M,1024] fp32 row-major -> out [M,3072] bf16:  [hi | lo | hi]
__global__ __launch_bounds__(256) void split_rows(const float* __restrict__ in,
                                                  __nv_bfloat16* __restrict__ out) {
    int idx = blockIdx.x * 256 + threadIdx.x;       // quad index
    int m  = idx >> 8;                               // 1024/4 = 256 quads/row
    int kq = idx & 255;
    float4 v = ((const float4*)in)[(size_t)m * 256 + kq];
    __nv_bfloat16 h0 = __float2bfloat16(v.x), h1 = __float2bfloat16(v.y);
    __nv_bfloat16 h2 = __float2bfloat16(v.z), h3 = __float2bfloat16(v.w);
    __nv_bfloat16 l0 = __float2bfloat16(v.x - __bfloat162float(h0));
    __nv_bfloat16 l1 = __float2bfloat16(v.y - __bfloat162float(h1));
    __nv_bfloat16 l2 = __float2bfloat16(v.z - __bfloat162float(h2));
    __nv_bfloat16 l3 = __float2bfloat16(v.w - __bfloat162float(h3));
    __nv_bfloat162 hA = {h0, h1}, hB = {h2, h3};
    __nv_bfloat162 lA = {l0, l1}, lB = {l2, l3};
    __nv_bfloat162* o = (__nv_bfloat162*)(out + (size_t)m * KSPLIT + kq * 4);
    o[0] = hA; o[1] = hB;                            // [0,1024): hi
    o[512] = lA; o[513] = lB;                        // [1024,2048): lo
    o[1024] = hA; o[1025] = hB;                      // [2048,3072): hi
}

// W [K,N] fp32 -> BT [N,3K] bf16 with [hi | hi | lo] along k'
__global__ __launch_bounds__(256) void split_bt(const float* __restrict__ W,
                                                __nv_bfloat16* __restrict__ BT,
                                                int K, int N) {
    __shared__ float tile[32][33];
    int k0 = blockIdx.x * 32, n0 = blockIdx.y * 32;
    for (int i = threadIdx.x; i < 1024; i += 256) {
        int r = i >> 5, c = i & 31;
        tile[r][c] = W[(size_t)(k0 + r) * N + n0 + c];
    }
    __syncthreads();
    for (int i = threadIdx.x; i < 1024; i += 256) {
        int rn = i >> 5, kc = i & 31;
        float v = tile[kc][rn];
        __nv_bfloat16 hi = __float2bfloat16(v);
        __nv_bfloat16 lo = __float2bfloat16(v - __bfloat162float(hi));
        __nv_bfloat16* row = BT + (size_t)(n0 + rn) * (3 * K) + k0 + kc;
        row[0]     = hi;
        row[K]     = hi;
        row[2 * K] = lo;
    }
}

// ==================== HMMA bf16 GEMM (mma.sync), 64x64 warp tiles ============
// C[M,N] fp32 = A[M,Kp] bf16 @ BT[N,Kp]^T bf16.
// CTA tile 128x128, BK=64 (128B rows, SW128), double-buffered cp.async.
// 128 threads = 4 warps in 2x2: warp tile 64x64. Per ks: 8 LDSM : 32 MMA.
__global__ __launch_bounds__(128) void bf16gemm_mma(const __nv_bfloat16* __restrict__ A,
                                                    const __nv_bfloat16* __restrict__ BT,
                                                    float* __restrict__ C,
                                                    int M, int N, int Kp) {
    extern __shared__ __align__(1024) char smem[];
    const uint32_t base = smem_u32(smem);
    const int tid  = threadIdx.x;
    const int wid  = tid >> 5;
    const int lane = tid & 31;
    const int wr   = wid >> 1;       // 0..1  (warp row -> 64 rows)
    const int wc   = wid & 1;        // 0..1  (warp col -> 64 cols)

    const int brow = blockIdx.y * 128;
    const int bcol = blockIdx.x * 128;
    const int nc   = Kp / 64;

    const __nv_bfloat16* Abase = A + (size_t)brow * Kp;
    const __nv_bfloat16* Bbase = BT + (size_t)bcol * Kp;

    auto load_stage = [&](int chunk, int s) {
        uint32_t sa = base + s * 32768;
        uint32_t sb = sa + 16384;
        const __nv_bfloat16* ac = Abase + chunk * 64;
        const __nv_bfloat16* bc = Bbase + chunk * 64;
        #pragma unroll
        for (int i = 0; i < 8; i++) {
            int l = tid + i * 128;
            int r = l >> 3;
            int c = l & 7;
            uint32_t sw = sw128((uint32_t)(r * 128 + c * 16));
            cp_async16(sa + sw, ac + (size_t)r * Kp + c * 8);
            cp_async16(sb + sw, bc + (size_t)r * Kp + c * 8);
        }
        cp_commit();
    };

    float acc[4][8][4];
    #pragma unroll
    for (int mi = 0; mi < 4; mi++)
        #pragma unroll
        for (int ni = 0; ni < 8; ni++)
            #pragma unroll
            for (int j = 0; j < 4; j++) acc[mi][ni][j] = 0.f;

    load_stage(0, 0);
    load_stage(1, 1);

    const int a_row_off = wr * 64 + (lane & 15);              // + mi*16
    const int a_chunk_h = lane >> 4;                          // + ks*2
    const int b_row_off = wc * 64 + ((lane >> 4) << 3) + (lane & 7);  // + g*16
    const int b_chunk_h = (lane >> 3) & 1;                    // + ks*2

    for (int c = 0; c < nc; c++) {
        int s = c & 1;
        if (c + 1 < nc) asm volatile("cp.async.wait_group 1;" ::: "memory");
        else            asm volatile("cp.async.wait_group 0;" ::: "memory");
        __syncthreads();

        uint32_t sa = base + s * 32768;
        uint32_t sb = sa + 16384;

        #pragma unroll
        for (int ks = 0; ks < 4; ks++) {
            uint32_t a[4][4];
            #pragma unroll
            for (int mi = 0; mi < 4; mi++) {
                uint32_t off = (uint32_t)((a_row_off + mi * 16) * 128
                                          + (ks * 2 + a_chunk_h) * 16);
                ldmatrix_x4(a[mi], sa + sw128(off));
            }
            uint32_t b[4][4];
            #pragma unroll
            for (int g = 0; g < 4; g++) {
                uint32_t off = (uint32_t)((b_row_off + g * 16) * 128
                                          + (ks * 2 + b_chunk_h) * 16);
                ldmatrix_x4(b[g], sb + sw128(off));
            }
            #pragma unroll
            for (int mi = 0; mi < 4; mi++)
                #pragma unroll
                for (int g = 0; g < 4; g++) {
                    mma16816(acc[mi][2 * g],     a[mi], b[g][0], b[g][1]);
                    mma16816(acc[mi][2 * g + 1], a[mi], b[g][2], b[g][3]);
                }
        }
        __syncthreads();
        if (c + 2 < nc) load_stage(c + 2, s);
    }

    #pragma unroll
    for (int mi = 0; mi < 4; mi++) {
        int row0 = brow + wr * 64 + mi * 16 + (lane >> 2);
        #pragma unroll
        for (int ni = 0; ni < 8; ni++) {
            int col = bcol + wc * 64 + ni * 8 + (lane & 3) * 2;
            float2 v0 = {acc[mi][ni][0], acc[mi][ni][1]};
            float2 v1 = {acc[mi][ni][2], acc[mi][ni][3]};
            *(float2*)(C + (size_t)row0 * N + col) = v0;
            *(float2*)(C + (size_t)(row0 + 8) * N + col) = v1;
        }
    }
}

// -------------------- RoPE: qkv -> split bf16 q (scaled), k  [bh,s,d] -------
// q is pre-scaled by 0.125 * log2(e) so flash softmax can use exp2f.
__global__ __launch_bounds__(256) void rope_qk(const float* __restrict__ qkv) {
    int gid = blockIdx.x * blockDim.x + threadIdx.x;   // 0 .. BS*INNER-1
    int d  = gid & 63;
    int h  = (gid >> 6) & (HEADS - 1);
    int bs = gid >> 10;
    int s  = bs & (SEQ - 1);
    int b  = bs >> 11;

    const float* row = qkv + (size_t)bs * QKV_N;
    float qv = row[h * 64 + d];
    float kv = row[INNER + h * 64 + d];

    int i = d & 31;
    float inv_freq = powf(10000.f, -(float)i / 32.f);
    float ang = (float)s * inv_freq;
    float c = cosf(ang), sn = sinf(ang);

    float qo, ko;
    if (d < 32) {
        float q2 = row[h * 64 + d + 32];
        float k2 = row[INNER + h * 64 + d + 32];
        qo = qv * c - q2 * sn;
        ko = kv * c - k2 * sn;
    } else {
        float q2 = row[h * 64 + d - 32];
        float k2 = row[INNER + h * 64 + d - 32];
        qo = qv * c + q2 * sn;
        ko = kv * c + k2 * sn;
    }
    qo *= 0.125f * 1.44269504088896f;   // fold softmax scale + log2e

    size_t o = (((size_t)(b * HEADS + h)) * SEQ + s) * DHEAD + d;
    __nv_bfloat16 qh = __float2bfloat16(qo);
    __nv_bfloat16 kh = __float2bfloat16(ko);
    g_qh[o] = qh;
    g_ql[o] = __float2bfloat16(qo - __bfloat162float(qh));
    g_kh[o] = kh;
    g_kl[o] = __float2bfloat16(ko - __bfloat162float(kh));
}

// -------------------- V: qkv -> transposed split bf16 V^T [bh,d,s] ----------
__global__ __launch_bounds__(256) void vsplit_t(const float* __restrict__ qkv) {
    __shared__ float tile[64][65];
    int bh = blockIdx.y;                 // 0..31
    int s0 = blockIdx.x * 64;            // seq tile
    int b = bh >> 4, h = bh & 15;
    int tid = threadIdx.x;

    for (int t = 0; t < 4; t++) {
        int l = tid + t * 256;
        int r = l >> 4;
        int c4 = (l & 15) * 4;
        float4 v = *(const float4*)(qkv + (size_t)(b * SEQ + s0 + r) * QKV_N
                                    + 2 * INNER + h * 64 + c4);
        tile[r][c4] = v.x; tile[r][c4 + 1] = v.y;
        tile[r][c4 + 2] = v.z; tile[r][c4 + 3] = v.w;
    }
    __syncthreads();

    for (int t = 0; t < 16; t++) {
        int l = tid + t * 256;
        int d = l >> 6, s = l & 63;
        float v = tile[s][d];
        __nv_bfloat16 hi = __float2bfloat16(v);
        size_t o = ((size_t)bh * DHEAD + d) * SEQ + s0 + s;
        g_vth[o] = hi;
        g_vtl[o] = __float2bfloat16(v - __bfloat162float(hi));
    }
}

// ==================== flash attention via HMMA (hi/lo split) =================
// Block: one (bh, 128-q tile). 4 warps x 32 q rows. KV tiles of 64, double buffered.
// SMEM: Qh(16K) Ql(16K) | stage0: kh kl vth vtl (4x8K) | stage1 (4x8K) = 96KB.
__global__ __launch_bounds__(128) void flash_mma(float* __restrict__ out) {
    extern __shared__ __align__(1024) char smem[];
    const uint32_t base = smem_u32(smem);
    const int tid  = threadIdx.x;
    const int wid  = tid >> 5;       // 0..3
    const int lane = tid & 31;
    const int bh = blockIdx.y;
    const int qt = blockIdx.x;
    const int b = bh >> 4, h = bh & 15;

    const __nv_bfloat16* qhp = g_qh + ((size_t)bh * SEQ + qt * 128) * DHEAD;
    const __nv_bfloat16* qlp = g_ql + ((size_t)bh * SEQ + qt * 128) * DHEAD;

    // load Q tiles (2 x 128 rows x 128B)
    #pragma unroll
    for (int t = 0; t < 8; t++) {
        int l = tid + t * 128;
        int r = l >> 3, c = l & 7;
        uint32_t sw = sw128((uint32_t)(r * 128 + c * 16));
        cp_async16(base + sw,         qhp + (size_t)r * DHEAD + c * 8);
        cp_async16(base + 16384 + sw, qlp + (size_t)r * DHEAD + c * 8);
    }
    cp_commit();

    auto load_kv = [&](int it, int s) {
        uint32_t st = base + 32768 + s * 32768;
        const __nv_bfloat16* khp = g_kh + ((size_t)bh * SEQ + it * 64) * DHEAD;
        const __nv_bfloat16* klp = g_kl + ((size_t)bh * SEQ + it * 64) * DHEAD;
        const __nv_bfloat16* vhp = g_vth + (size_t)bh * DHEAD * SEQ + it * 64;
        const __nv_bfloat16* vlp = g_vtl + (size_t)bh * DHEAD * SEQ + it * 64;
        #pragma unroll
        for (int t = 0; t < 4; t++) {
            int l = tid + t * 128;       // 512 chunks per tile
            int r = l >> 3, c = l & 7;
            uint32_t sw = sw128((uint32_t)(r * 128 + c * 16));
            cp_async16(st + sw,          khp + (size_t)r * DHEAD + c * 8);
            cp_async16(st + 8192 + sw,   klp + (size_t)r * DHEAD + c * 8);
            cp_async16(st + 16384 + sw,  vhp + (size_t)r * SEQ + c * 8);
            cp_async16(st + 24576 + sw,  vlp + (size_t)r * SEQ + c * 8);
        }
        cp_commit();
    };

    load_kv(0, 0);
    load_kv(1, 1);

    const int a_row  = wid * 32 + (lane & 15);        // + mi*16
    const int a_chh  = lane >> 4;
    const int b_row  = ((lane >> 4) << 3) + (lane & 7);
    const int b_chh  = (lane >> 3) & 1;

    float Oacc[2][8][4];
    #pragma unroll
    for (int mi = 0; mi < 2; mi++)
        #pragma unroll
        for (int n = 0; n < 8; n++)
            #pragma unroll
            for (int j = 0; j < 4; j++) Oacc[mi][n][j] = 0.f;
    float mrow[2][2] = {{-INFINITY, -INFINITY}, {-INFINITY, -INFINITY}};
    float lrow[2][2] = {{0.f, 0.f}, {0.f, 0.f}};

    const int nIter = SEQ / 64;
    for (int it = 0; it < nIter; it++) {
        int s = it & 1;
        if (it + 1 < nIter) asm volatile("cp.async.wait_group 1;" ::: "memory");
        else                asm volatile("cp.async.wait_group 0;" ::: "memory");
        __syncthreads();

        uint32_t st  = base + 32768 + s * 32768;
        uint32_t sqh = base, sql = base + 16384;
        uint32_t skh = st, skl = st + 8192, svh = st + 16384, svl = st + 24576;

        // ---- S = Qh Kh^T + Ql Kh^T + Qh Kl^T  (log2-scaled scores) ----
        float sacc[2][8][4];
        #pragma unroll
        for (int mi = 0; mi < 2; mi++)
            #pragma unroll
            for (int n = 0; n < 8; n++)
                #pragma unroll
                for (int j = 0; j < 4; j++) sacc[mi][n][j] = 0.f;

        #pragma unroll
        for (int pass = 0; pass < 3; pass++) {
            uint32_t at = (pass == 1) ? sql : sqh;
            uint32_t bt = (pass == 2) ? skl : skh;
            #pragma unroll
            for (int ks = 0; ks < 4; ks++) {
                uint32_t a[2][4];
                #pragma unroll
                for (int mi = 0; mi < 2; mi++)
                    ldmatrix_x4(a[mi], at + sw128((uint32_t)((a_row + mi * 16) * 128
                                                  + (ks * 2 + a_chh) * 16)));
                #pragma unroll
                for (int g = 0; g < 4; g++) {
                    uint32_t bb[4];
                    ldmatrix_x4(bb, bt + sw128((uint32_t)((g * 16 + b_row) * 128
                                               + (ks * 2 + b_chh) * 16)));
                    #pragma unroll
                    for (int mi = 0; mi < 2; mi++) {
                        mma16816(sacc[mi][2 * g],     a[mi], bb[0], bb[1]);
                        mma16816(sacc[mi][2 * g + 1], a[mi], bb[2], bb[3]);
                    }
                }
            }
        }

        // ---- register online softmax (exp2 domain) ----
        uint32_t pah[2][4][4], pal[2][4][4];
        #pragma unroll
        for (int mi = 0; mi < 2; mi++) {
            float mx0 = mrow[mi][0], mx1 = mrow[mi][1];
            #pragma unroll
            for (int n = 0; n < 8; n++) {
                mx0 = fmaxf(mx0, fmaxf(sacc[mi][n][0], sacc[mi][n][1]));
                mx1 = fmaxf(mx1, fmaxf(sacc[mi][n][2], sacc[mi][n][3]));
            }
            mx0 = fmaxf(mx0, __shfl_xor_sync(0xffffffff, mx0, 1));
            mx0 = fmaxf(mx0, __shfl_xor_sync(0xffffffff, mx0, 2));
            mx1 = fmaxf(mx1, __shfl_xor_sync(0xffffffff, mx1, 1));
            mx1 = fmaxf(mx1, __shfl_xor_sync(0xffffffff, mx1, 2));
            float corr0 = exp2f(mrow[mi][0] - mx0);
            float corr1 = exp2f(mrow[mi][1] - mx1);
            mrow[mi][0] = mx0; mrow[mi][1] = mx1;

            float sum0 = 0.f, sum1 = 0.f;
            #pragma unroll
            for (int n = 0; n < 8; n++) {
                float p0 = exp2f(sacc[mi][n][0] - mx0);
                float p1 = exp2f(sacc[mi][n][1] - mx0);
                float p2 = exp2f(sacc[mi][n][2] - mx1);
                float p3 = exp2f(sacc[mi][n][3] - mx1);
                sum0 += p0 + p1; sum1 += p2 + p3;
                __nv_bfloat16 h0 = __float2bfloat16(p0), h1 = __float2bfloat16(p1);
                __nv_bfloat16 h2 = __float2bfloat16(p2), h3 = __float2bfloat16(p3);
                int ks = n >> 1, hf = (n & 1) * 2;
                __nv_bfloat162 ph01 = {h0, h1}, ph23 = {h2, h3};
                pah[mi][ks][hf]     = *(uint32_t*)&ph01;
                pah[mi][ks][hf + 1] = *(uint32_t*)&ph23;
                __nv_bfloat162 pl01 = {__float2bfloat16(p0 - __bfloat162float(h0)),
                                       __float2bfloat16(p1 - __bfloat162float(h1))};
                __nv_bfloat162 pl23 = {__float2bfloat16(p2 - __bfloat162float(h2)),
                                       __float2bfloat16(p3 - __bfloat162float(h3))};
                pal[mi][ks][hf]     = *(uint32_t*)&pl01;
                pal[mi][ks][hf + 1] = *(uint32_t*)&pl23;
            }
            lrow[mi][0] = lrow[mi][0] * corr0 + sum0;
            lrow[mi][1] = lrow[mi][1] * corr1 + sum1;
            #pragma unroll
            for (int n = 0; n < 8; n++) {
                Oacc[mi][n][0] *= corr0; Oacc[mi][n][1] *= corr0;
                Oacc[mi][n][2] *= corr1; Oacc[mi][n][3] *= corr1;
            }
        }

        // ---- O += Ph Vh + Pl Vh + Ph Vl ----
        #pragma unroll
        for (int ks = 0; ks < 4; ks++) {
            #pragma unroll
            for (int g = 0; g < 4; g++) {
                uint32_t off = (uint32_t)((g * 16 + b_row) * 128 + (ks * 2 + b_chh) * 16);
                uint32_t bh_[4], bl_[4];
                ldmatrix_x4(bh_, svh + sw128(off));
                ldmatrix_x4(bl_, svl + sw128(off));
                #pragma unroll
                for (int mi = 0; mi < 2; mi++) {
                    mma16816(Oacc[mi][2 * g],     pah[mi][ks], bh_[0], bh_[1]);
                    mma16816(Oacc[mi][2 * g + 1], pah[mi][ks], bh_[2], bh_[3]);
                    mma16816(Oacc[mi][2 * g],     pal[mi][ks], bh_[0], bh_[1]);
                    mma16816(Oacc[mi][2 * g + 1], pal[mi][ks], bh_[2], bh_[3]);
                    mma16816(Oacc[mi][2 * g],     pah[mi][ks], bl_[0], bl_[1]);
                    mma16816(Oacc[mi][2 * g + 1], pah[mi][ks], bl_[2], bl_[3]);
                }
            }
        }

        __syncthreads();
        if (it + 2 < nIter) load_kv(it + 2, s);
    }

    // final normalize + write ctx [B,S,H*Dh]
    #pragma unroll
    for (int mi = 0; mi < 2; mi++) {
        float l0 = lrow[mi][0], l1 = lrow[mi][1];
        l0 += __shfl_xor_sync(0xffffffff, l0, 1);
        l0 += __shfl_xor_sync(0xffffffff, l0, 2);
        l1 += __shfl_xor_sync(0xffffffff, l1, 1);
        l1 += __shfl_xor_sync(0xffffffff, l1, 2);
        float inv0 = 1.f / l0, inv1 = 1.f / l1;
        int row0 = qt * 128 + wid * 32 + mi * 16 + (lane >> 2);
        #pragma unroll
        for (int n = 0; n < 8; n++) {
            int col = h * 64 + n * 8 + (lane & 3) * 2;
            float2 v0 = {Oacc[mi][n][0] * inv0, Oacc[mi][n][1] * inv0};
            float2 v1 = {Oacc[mi][n][2] * inv1, Oacc[mi][n][3] * inv1};
            *(float2*)(out + ((size_t)(b * SEQ + row0)) * INNER + col) = v0;
            *(float2*)(out + ((size_t)(b * SEQ + row0 + 8)) * INNER + col) = v1;
        }
    }
}

// -------------------- launch --------------------
extern "C" void kernel_launch(void* const* d_in, const int* in_sizes, int n_in,
                              void* d_out, int out_size) {
    const float* x     = (const float*)d_in[0];   // [2,2048,1024]
    const float* w_qkv = (const float*)d_in[1];   // [1024,3072]
    const float* w_out = (const float*)d_in[2];   // [1024,1024]
    float* out = (float*)d_out;                   // [2,2048,1024]

    float *qkv, *ctx;
    __nv_bfloat16 *abuf, *btq, *bto;
    cudaGetSymbolAddress((void**)&qkv,  g_qkv);
    cudaGetSymbolAddress((void**)&ctx,  g_ctx);
    cudaGetSymbolAddress((void**)&abuf, g_abuf);
    cudaGetSymbolAddress((void**)&btq,  g_bt_qkv);
    cudaGetSymbolAddress((void**)&bto,  g_bt_out);

    const int kGemmSmem = 2 * 32768;   // 64 KB
    cudaFuncSetAttribute(bf16gemm_mma, cudaFuncAttributeMaxDynamicSharedMemorySize, kGemmSmem);
    const int kFlashSmem = 32768 + 2 * 32768;   // 96 KB
    cudaFuncSetAttribute(flash_mma, cudaFuncAttributeMaxDynamicSharedMemorySize, kFlashSmem);

    // weight conversions (hi/lo split + transpose)
    split_bt<<<dim3(DMODEL / 32, QKV_N / 32), 256>>>(w_qkv, btq, DMODEL, QKV_N);
    split_bt<<<dim3(INNER / 32, DMODEL / 32), 256>>>(w_out, bto, INNER, DMODEL);

    // 1) qkv = x @ w_qkv  via bf16 3-split HMMA GEMM
    split_rows<<<(BS * DMODEL / 4) / 256, 256>>>(x, abuf);
    bf16gemm_mma<<<dim3(QKV_N / 128, BS / 128), 128, kGemmSmem>>>(abuf, btq, qkv, BS, QKV_N, KSPLIT);

    // 2) RoPE + hi/lo split of q,k; transposed split of v
    rope_qk<<<(BS * INNER) / 256, 256>>>(qkv);
    vsplit_t<<<dim3(SEQ / 64, BH), 256>>>(qkv);

    // 3) flash attention via HMMA
    flash_mma<<<dim3(SEQ / 128, BH), 128, kFlashSmem>>>(ctx);

    // 4) out = ctx @ w_out  via bf16 3-split HMMA GEMM
    split_rows<<<(BS * INNER / 4) / 256, 256>>>(ctx, abuf);
    bf16gemm_mma<<<dim3(DMODEL / 128, BS / 128), 128, kGemmSmem>>>(abuf, bto, out, BS, DMODEL, KSPLIT);
}